// round 10
// baseline (speedup 1.0000x reference)
#include <cuda_runtime.h>

// PeriodicConvolutionPrep:
//   out[p] = sum_d W[d] @ ( sum_{j<16} radii[p*16+j, d] * features[nbr[p][j]] )
//
// Inputs (metadata order):
//   d_in[0] features : float32 [40000, 16]
//   d_in[1] radii    : float32 [640000, 3]
//   d_in[2] W        : float32 [3, 16, 16]   (W[d][o][i])
//   d_in[3] bs_slice : int32   [40000, 17]   (col 0 = count(=16), cols 1.. = nbr idx)
// Output: float32 [40000, 16]
//
// Mapping: 4 lanes per point; lane q owns channels [4q, 4q+4) as float4.
// R7 profile: all units <50%, occ 23% -> latency-limited. This round: grid 625->1250
// (128-thr blocks), single 16-deep gather batch, radii loads hidden under gathers.

#define NPTS 40000
#define DEG 16
#define CI 16
#define CO 16
#define LANES_PER_PT 4
#define PTS_PER_BLOCK 32
#define NTHREADS (PTS_PER_BLOCK * LANES_PER_PT)   // 128

__device__ __forceinline__ float f4_get(const float4& v, int m) {
    // m is compile-time constant under full unroll -> folds to a register read.
    return (m == 0) ? v.x : (m == 1) ? v.y : (m == 2) ? v.z : v.w;
}

__global__ __launch_bounds__(NTHREADS)
void periodic_conv_kernel(const float* __restrict__ features,
                          const float* __restrict__ radii,
                          const float* __restrict__ W,
                          const int*   __restrict__ bs,
                          float*       __restrict__ out)
{
    // Wt[(i*3 + d)*16 + c] = W[d][c][i]; epilogue reads it as float4 of 4 channels.
    __shared__ float Wt[CI * 3 * CO];   // 768 floats = 3 KB

    const int tid = threadIdx.x;
    #pragma unroll
    for (int t = tid; t < CI * 3 * CO; t += NTHREADS) {
        const int i   = t / 48;
        const int rem = t % 48;
        const int d   = rem / 16;
        const int c   = rem % 16;
        Wt[t] = __ldg(W + d * (CO * CI) + c * CI + i);
    }
    __syncthreads();

    const int p = blockIdx.x * PTS_PER_BLOCK + (tid >> 2);  // 40000 % 32 == 0, no tail
    const int q = tid & 3;                                  // lane within point quad

    // Neighbor indices: lane q holds j in [4q, 4q+4). Read-once -> evict-first.
    const int* brow = bs + (size_t)p * 17 + 1;
    int nbr_reg[4];
    #pragma unroll
    for (int m = 0; m < 4; m++) nbr_reg[m] = __ldcs(brow + 4 * q + m);

    // Distribute all 16 neighbor indices (sources resolve once nbr_reg lands).
    int nbr[DEG];
    #pragma unroll
    for (int j = 0; j < DEG; j++)
        nbr[j] = __shfl_sync(0xffffffffu, nbr_reg[j & 3], j >> 2, LANES_PER_PT);

    // Single batch: issue ALL 16 independent 16B gathers back-to-back (MLP=16);
    // one latency exposure instead of two.
    float4 f[DEG];
    #pragma unroll
    for (int j = 0; j < DEG; j++)
        f[j] = __ldg((const float4*)(features + (size_t)nbr[j] * CI) + q);

    // Radii issued AFTER the gathers: their latency hides under the gather batch.
    // 48 floats per point; lane q holds flat elements [12q, 12q+12) as 3 float4.
    // Element k = j*3 + d  ->  src lane k/12, local reg (k%12)>>2, component (k%12)&3.
    const float4* rbase = (const float4*)(radii + (size_t)p * (DEG * 3));
    const float4 rA = __ldcs(rbase + 3 * q + 0);
    const float4 rB = __ldcs(rbase + 3 * q + 1);
    const float4 rC = __ldcs(rbase + 3 * q + 2);

    float4 g0 = {0.f, 0.f, 0.f, 0.f};   // g_d[4q..4q+3] = sum_j radii[j,d]*f[nbr_j][4q..4q+3]
    float4 g1 = {0.f, 0.f, 0.f, 0.f};
    float4 g2 = {0.f, 0.f, 0.f, 0.f};

    #pragma unroll
    for (int j = 0; j < DEG; j++) {
        #pragma unroll
        for (int d = 0; d < 3; d++) {
            const int k    = 3 * j + d;
            const int lane = k / 12;
            const int rem  = k % 12;
            const float v  = (rem < 4) ? f4_get(rA, rem & 3)
                           : (rem < 8) ? f4_get(rB, rem & 3)
                                       : f4_get(rC, rem & 3);
            const float r = __shfl_sync(0xffffffffu, v, lane, LANES_PER_PT);
            float4& g = (d == 0) ? g0 : (d == 1) ? g1 : g2;
            g.x = fmaf(r, f[j].x, g.x);
            g.y = fmaf(r, f[j].y, g.y);
            g.z = fmaf(r, f[j].z, g.z);
            g.w = fmaf(r, f[j].w, g.w);
        }
    }

    // Epilogue: out[p][4q+t] = sum_d sum_i W[d][4q+t][i] * g_d[i].
    // g_d[i] lives in lane i>>2, component i&3.
    const float4* Wt4 = (const float4*)Wt;
    float4 acc = {0.f, 0.f, 0.f, 0.f};
    #pragma unroll
    for (int i = 0; i < CI; i++) {
        const int src = i >> 2;
        const int m   = i & 3;
        const float gv0 = __shfl_sync(0xffffffffu, f4_get(g0, m), src, LANES_PER_PT);
        const float gv1 = __shfl_sync(0xffffffffu, f4_get(g1, m), src, LANES_PER_PT);
        const float gv2 = __shfl_sync(0xffffffffu, f4_get(g2, m), src, LANES_PER_PT);
        const float4 w0 = Wt4[(i * 3 + 0) * 4 + q];
        const float4 w1 = Wt4[(i * 3 + 1) * 4 + q];
        const float4 w2 = Wt4[(i * 3 + 2) * 4 + q];
        acc.x = fmaf(w0.x, gv0, acc.x); acc.y = fmaf(w0.y, gv0, acc.y);
        acc.z = fmaf(w0.z, gv0, acc.z); acc.w = fmaf(w0.w, gv0, acc.w);
        acc.x = fmaf(w1.x, gv1, acc.x); acc.y = fmaf(w1.y, gv1, acc.y);
        acc.z = fmaf(w1.z, gv1, acc.z); acc.w = fmaf(w1.w, gv1, acc.w);
        acc.x = fmaf(w2.x, gv2, acc.x); acc.y = fmaf(w2.y, gv2, acc.y);
        acc.z = fmaf(w2.z, gv2, acc.z); acc.w = fmaf(w2.w, gv2, acc.w);
    }

    // Output is write-once, never re-read here: stream past L1.
    __stcg((float4*)(out + (size_t)p * CO) + q, acc);
}

extern "C" void kernel_launch(void* const* d_in, const int* in_sizes, int n_in,
                              void* d_out, int out_size)
{
    const float* features = (const float*)d_in[0];
    const float* radii    = (const float*)d_in[1];
    const float* W        = (const float*)d_in[2];
    const int*   bs       = (const int*)d_in[3];
    float*       out      = (float*)d_out;

    // Only 3 KB smem used: maximize the L1 data-cache carveout for the
    // feature-gather working set (2.56 MB, re-read ~16x).
    cudaFuncSetAttribute(periodic_conv_kernel,
                         cudaFuncAttributePreferredSharedMemoryCarveout,
                         cudaSharedmemCarveoutMaxL1);

    periodic_conv_kernel<<<NPTS / PTS_PER_BLOCK, NTHREADS>>>(features, radii, W, bs, out);
}

// round 13
// speedup vs baseline: 1.1236x; 1.1236x over previous
#include <cuda_runtime.h>

// PeriodicConvolutionPrep:
//   out[p] = sum_d W[d] @ ( sum_{j<16} radii[p*16+j, d] * features[nbr[p][j]] )
//
// Inputs (metadata order):
//   d_in[0] features : float32 [40000, 16]
//   d_in[1] radii    : float32 [640000, 3]
//   d_in[2] W        : float32 [3, 16, 16]   (W[d][o][i])
//   d_in[3] bs_slice : int32   [40000, 17]   (col 0 = count(=16), cols 1.. = nbr idx)
// Output: float32 [40000, 16]
//
// Mapping: 4 lanes per point; lane q owns channels [4q, 4q+4) as float4.
//
// R7/R10 post-mortem: the cudaSharedmemCarveoutMaxL1 hint pinned the smem
// carveout to ~8KB/SM -> hard 2 CTA/SM cap (occ 23%/12%). Hint removed.
// 256-thread blocks hedge both hypotheses: reg-limited -> 4 CTAs = 32 warps/SM;
// residual 2-CTA cap -> still 16 warps/SM (R7 level, not R10's 8).

#define NPTS 40000
#define DEG 16
#define CI 16
#define CO 16
#define LANES_PER_PT 4
#define PTS_PER_BLOCK 64
#define NTHREADS (PTS_PER_BLOCK * LANES_PER_PT)   // 256

__device__ __forceinline__ float f4_get(const float4& v, int m) {
    // m is compile-time constant under full unroll -> folds to a register read.
    return (m == 0) ? v.x : (m == 1) ? v.y : (m == 2) ? v.z : v.w;
}

__global__ __launch_bounds__(NTHREADS)
void periodic_conv_kernel(const float* __restrict__ features,
                          const float* __restrict__ radii,
                          const float* __restrict__ W,
                          const int*   __restrict__ bs,
                          float*       __restrict__ out)
{
    // Wt[(i*3 + d)*16 + c] = W[d][c][i]; epilogue reads it as float4 of 4 channels.
    __shared__ float Wt[CI * 3 * CO];   // 768 floats = 3 KB

    const int tid = threadIdx.x;
    #pragma unroll
    for (int t = tid; t < CI * 3 * CO; t += NTHREADS) {
        const int i   = t / 48;
        const int rem = t % 48;
        const int d   = rem / 16;
        const int c   = rem % 16;
        Wt[t] = __ldg(W + d * (CO * CI) + c * CI + i);
    }
    __syncthreads();

    const int p = blockIdx.x * PTS_PER_BLOCK + (tid >> 2);  // 40000 % 64 == 0, no tail
    const int q = tid & 3;                                  // lane within point quad

    // Neighbor indices: lane q holds j in [4q, 4q+4). Read-once -> evict-first.
    const int* brow = bs + (size_t)p * 17 + 1;
    int nbr_reg[4];
    #pragma unroll
    for (int m = 0; m < 4; m++) nbr_reg[m] = __ldcs(brow + 4 * q + m);

    // Distribute all 16 neighbor indices (sources resolve once nbr_reg lands).
    int nbr[DEG];
    #pragma unroll
    for (int j = 0; j < DEG; j++)
        nbr[j] = __shfl_sync(0xffffffffu, nbr_reg[j & 3], j >> 2, LANES_PER_PT);

    // Issue all 16 independent 16B gathers up front (ptxas schedules within its
    // register budget; warp count is the primary latency-hiding lever).
    float4 f[DEG];
    #pragma unroll
    for (int j = 0; j < DEG; j++)
        f[j] = __ldg((const float4*)(features + (size_t)nbr[j] * CI) + q);

    // Radii issued AFTER the gathers: their latency hides under the gather batch.
    // 48 floats per point; lane q holds flat elements [12q, 12q+12) as 3 float4.
    // Element k = j*3 + d  ->  src lane k/12, local reg (k%12)>>2, component (k%12)&3.
    const float4* rbase = (const float4*)(radii + (size_t)p * (DEG * 3));
    const float4 rA = __ldcs(rbase + 3 * q + 0);
    const float4 rB = __ldcs(rbase + 3 * q + 1);
    const float4 rC = __ldcs(rbase + 3 * q + 2);

    float4 g0 = {0.f, 0.f, 0.f, 0.f};   // g_d[4q..4q+3] = sum_j radii[j,d]*f[nbr_j][4q..4q+3]
    float4 g1 = {0.f, 0.f, 0.f, 0.f};
    float4 g2 = {0.f, 0.f, 0.f, 0.f};

    #pragma unroll
    for (int j = 0; j < DEG; j++) {
        #pragma unroll
        for (int d = 0; d < 3; d++) {
            const int k    = 3 * j + d;
            const int lane = k / 12;
            const int rem  = k % 12;
            const float v  = (rem < 4) ? f4_get(rA, rem & 3)
                           : (rem < 8) ? f4_get(rB, rem & 3)
                                       : f4_get(rC, rem & 3);
            const float r = __shfl_sync(0xffffffffu, v, lane, LANES_PER_PT);
            float4& g = (d == 0) ? g0 : (d == 1) ? g1 : g2;
            g.x = fmaf(r, f[j].x, g.x);
            g.y = fmaf(r, f[j].y, g.y);
            g.z = fmaf(r, f[j].z, g.z);
            g.w = fmaf(r, f[j].w, g.w);
        }
    }

    // Epilogue: out[p][4q+t] = sum_d sum_i W[d][4q+t][i] * g_d[i].
    // g_d[i] lives in lane i>>2, component i&3.
    const float4* Wt4 = (const float4*)Wt;
    float4 acc = {0.f, 0.f, 0.f, 0.f};
    #pragma unroll
    for (int i = 0; i < CI; i++) {
        const int src = i >> 2;
        const int m   = i & 3;
        const float gv0 = __shfl_sync(0xffffffffu, f4_get(g0, m), src, LANES_PER_PT);
        const float gv1 = __shfl_sync(0xffffffffu, f4_get(g1, m), src, LANES_PER_PT);
        const float gv2 = __shfl_sync(0xffffffffu, f4_get(g2, m), src, LANES_PER_PT);
        const float4 w0 = Wt4[(i * 3 + 0) * 4 + q];
        const float4 w1 = Wt4[(i * 3 + 1) * 4 + q];
        const float4 w2 = Wt4[(i * 3 + 2) * 4 + q];
        acc.x = fmaf(w0.x, gv0, acc.x); acc.y = fmaf(w0.y, gv0, acc.y);
        acc.z = fmaf(w0.z, gv0, acc.z); acc.w = fmaf(w0.w, gv0, acc.w);
        acc.x = fmaf(w1.x, gv1, acc.x); acc.y = fmaf(w1.y, gv1, acc.y);
        acc.z = fmaf(w1.z, gv1, acc.z); acc.w = fmaf(w1.w, gv1, acc.w);
        acc.x = fmaf(w2.x, gv2, acc.x); acc.y = fmaf(w2.y, gv2, acc.y);
        acc.z = fmaf(w2.z, gv2, acc.z); acc.w = fmaf(w2.w, gv2, acc.w);
    }

    // Output is write-once, never re-read here: stream past L1.
    __stcg((float4*)(out + (size_t)p * CO) + q, acc);
}

extern "C" void kernel_launch(void* const* d_in, const int* in_sizes, int n_in,
                              void* d_out, int out_size)
{
    const float* features = (const float*)d_in[0];
    const float* radii    = (const float*)d_in[1];
    const float* W        = (const float*)d_in[2];
    const int*   bs       = (const int*)d_in[3];
    float*       out      = (float*)d_out;

    // NOTE: no smem-carveout hint. cudaSharedmemCarveoutMaxL1 shrank the smem
    // carveout to ~8KB/SM and capped residency at 2 CTAs/SM (R7/R10 profiles).
    periodic_conv_kernel<<<NPTS / PTS_PER_BLOCK, NTHREADS>>>(features, radii, W, bs, out);
}